// round 13
// baseline (speedup 1.0000x reference)
#include <cuda_runtime.h>

// Device-global scratch (no allocations). Zero-init at load; last block resets
// after writing out, so graph replays stay deterministic.
__device__ unsigned long long g_mismatch_count = 0ULL;
__device__ unsigned int g_blocks_arrived = 0u;

__device__ __forceinline__ int group_of(int c) {
    return (c < 3) ? 0 : ((c < 6) ? 1 : 2);
}

__device__ __forceinline__ unsigned int mismatch(float4 a, float4 b, int t) {
    float m = a.x; int am = 0;
    if (a.y > m) { m = a.y; am = 1; }
    if (a.z > m) { m = a.z; am = 2; }
    if (a.w > m) { m = a.w; am = 3; }
    if (b.x > m) { m = b.x; am = 4; }
    if (b.y > m) { m = b.y; am = 5; }
    if (b.z > m) { m = b.z; am = 6; }
    if (b.w > m) { m = b.w; am = 7; }
    return (group_of(am) != group_of(t)) ? 1u : 0u;
}

// asm-volatile loads: pinned issue order among themselves.
__device__ __forceinline__ void ld_row(const float4* __restrict__ p,
                                       float4& a, float4& b) {
    asm volatile("ld.global.nc.v4.f32 {%0,%1,%2,%3}, [%4];"
                 : "=f"(a.x), "=f"(a.y), "=f"(a.z), "=f"(a.w)
                 : "l"(p));
    asm volatile("ld.global.nc.v4.f32 {%0,%1,%2,%3}, [%4];"
                 : "=f"(b.x), "=f"(b.y), "=f"(b.z), "=f"(b.w)
                 : "l"(p + 1));
}

__device__ __forceinline__ int ld_tgt(const int* __restrict__ p) {
    int v;
    asm volatile("ld.global.nc.b32 %0, [%1];" : "=r"(v) : "l"(p));
    return v;
}

// __launch_bounds__(256, 4): 4 blocks/SM target -> ~64-reg budget, so the
// 8-row front batch (16 float4 + 8 int live) can actually be allocated.
__global__ void __launch_bounds__(256, 4) path_loss_fused_kernel(
    const float4* __restrict__ preds,   // [batch * 2] float4 (row = 32B)
    const int* __restrict__ targets,    // [batch] int32
    float* __restrict__ out,
    int batch)
{
    int gid = blockIdx.x * blockDim.x + threadIdx.x;
    int S = gridDim.x * blockDim.x;

    unsigned int local = 0;

    // 8 stride-separated rows per iteration, all 24 loads front-batched.
    int i = gid;
    for (; i + 7 * S < batch; i += 8 * S) {
        float4 a[8], b[8];
        int t[8];
        #pragma unroll
        for (int k = 0; k < 8; k++)
            ld_row(preds + 2 * (i + k * S), a[k], b[k]);
        #pragma unroll
        for (int k = 0; k < 8; k++)
            t[k] = ld_tgt(targets + i + k * S);
        #pragma unroll
        for (int k = 0; k < 8; k++)
            local += mismatch(a[k], b[k], t[k]);
    }
    // Tail: per-row grid-stride.
    for (; i < batch; i += S) {
        float4 a, b;
        ld_row(preds + 2 * i, a, b);
        local += mismatch(a, b, ld_tgt(targets + i));
    }

    // warp reduction
    #pragma unroll
    for (int off = 16; off > 0; off >>= 1)
        local += __shfl_down_sync(0xFFFFFFFFu, local, off);

    __shared__ unsigned int warp_sums[8];
    int lane = threadIdx.x & 31;
    int wid = threadIdx.x >> 5;
    if (lane == 0) warp_sums[wid] = local;
    __syncthreads();

    if (wid == 0) {
        unsigned int v = (lane < (blockDim.x >> 5)) ? warp_sums[lane] : 0u;
        #pragma unroll
        for (int off = 4; off > 0; off >>= 1)
            v += __shfl_down_sync(0xFFFFFFFFu, v, off);

        if (lane == 0) {
            atomicAdd(&g_mismatch_count, (unsigned long long)v);
            __threadfence();
            unsigned int ticket = atomicAdd(&g_blocks_arrived, 1u);
            if (ticket == gridDim.x - 1) {
                unsigned long long total = atomicAdd(&g_mismatch_count, 0ULL);
                *out = (float)((double)total / (double)batch);
                g_mismatch_count = 0ULL;
                g_blocks_arrived = 0u;
            }
        }
    }
}

extern "C" void kernel_launch(void* const* d_in, const int* in_sizes, int n_in,
                              void* d_out, int out_size) {
    const float4* preds = (const float4*)d_in[0];   // [B, 8] f32
    const int* targets = (const int*)d_in[1];       // [B] int32
    int batch = in_sizes[0] / 8;
    float* out = (float*)d_out;

    const int threads = 256;
    // Persistent single wave: 148 SMs x 4 blocks/SM resident.
    int blocks = 148 * 4;
    path_loss_fused_kernel<<<blocks, threads>>>(preds, targets, out, batch);
}

// round 15
// speedup vs baseline: 1.0099x; 1.0099x over previous
#include <cuda_runtime.h>

// Device-global scratch (no allocations). Zero-init at load; last block resets
// after writing out, so graph replays stay deterministic.
__device__ unsigned long long g_mismatch_count = 0ULL;
__device__ unsigned int g_blocks_arrived = 0u;

__device__ __forceinline__ int group_of(int c) {
    return (c < 3) ? 0 : ((c < 6) ? 1 : 2);
}

__device__ __forceinline__ unsigned int mismatch(float4 a, float4 b, int t) {
    float m = a.x; int am = 0;
    if (a.y > m) { m = a.y; am = 1; }
    if (a.z > m) { m = a.z; am = 2; }
    if (a.w > m) { m = a.w; am = 3; }
    if (b.x > m) { m = b.x; am = 4; }
    if (b.y > m) { m = b.y; am = 5; }
    if (b.z > m) { m = b.z; am = 6; }
    if (b.w > m) { m = b.w; am = 7; }
    return (group_of(am) != group_of(t)) ? 1u : 0u;
}

// asm-volatile loads: pinned issue order among themselves.
__device__ __forceinline__ void ld_row(const float4* __restrict__ p,
                                       float4& a, float4& b) {
    asm volatile("ld.global.nc.v4.f32 {%0,%1,%2,%3}, [%4];"
                 : "=f"(a.x), "=f"(a.y), "=f"(a.z), "=f"(a.w)
                 : "l"(p));
    asm volatile("ld.global.nc.v4.f32 {%0,%1,%2,%3}, [%4];"
                 : "=f"(b.x), "=f"(b.y), "=f"(b.z), "=f"(b.w)
                 : "l"(p + 1));
}

__device__ __forceinline__ int ld_tgt(const int* __restrict__ p) {
    int v;
    asm volatile("ld.global.nc.b32 %0, [%1];" : "=r"(v) : "l"(p));
    return v;
}

// __launch_bounds__(256, 4): 4 blocks/SM target -> 64-reg budget so the 8-row
// front batch (16 float4 + 8 int live) is genuinely allocated (verified:
// regs=64 in profile, vs 32 without).
__global__ void __launch_bounds__(256, 4) path_loss_fused_kernel(
    const float4* __restrict__ preds,   // [batch * 2] float4 (row = 32B)
    const int* __restrict__ targets,    // [batch] int32
    float* __restrict__ out,
    int batch)
{
    int gid = blockIdx.x * blockDim.x + threadIdx.x;
    int S = gridDim.x * blockDim.x;

    unsigned int local = 0;

    // 8 stride-separated rows per iteration, all 24 loads front-batched.
    int i = gid;
    for (; i + 7 * S < batch; i += 8 * S) {
        float4 a[8], b[8];
        int t[8];
        #pragma unroll
        for (int k = 0; k < 8; k++)
            ld_row(preds + 2 * (i + k * S), a[k], b[k]);
        #pragma unroll
        for (int k = 0; k < 8; k++)
            t[k] = ld_tgt(targets + i + k * S);
        #pragma unroll
        for (int k = 0; k < 8; k++)
            local += mismatch(a[k], b[k], t[k]);
    }
    // Tail: per-row grid-stride.
    for (; i < batch; i += S) {
        float4 a, b;
        ld_row(preds + 2 * i, a, b);
        local += mismatch(a, b, ld_tgt(targets + i));
    }

    // warp reduction
    #pragma unroll
    for (int off = 16; off > 0; off >>= 1)
        local += __shfl_down_sync(0xFFFFFFFFu, local, off);

    __shared__ unsigned int warp_sums[8];
    int lane = threadIdx.x & 31;
    int wid = threadIdx.x >> 5;
    if (lane == 0) warp_sums[wid] = local;
    __syncthreads();

    if (wid == 0) {
        unsigned int v = (lane < (blockDim.x >> 5)) ? warp_sums[lane] : 0u;
        #pragma unroll
        for (int off = 4; off > 0; off >>= 1)
            v += __shfl_down_sync(0xFFFFFFFFu, v, off);

        if (lane == 0) {
            atomicAdd(&g_mismatch_count, (unsigned long long)v);
            __threadfence();
            unsigned int ticket = atomicAdd(&g_blocks_arrived, 1u);
            if (ticket == gridDim.x - 1) {
                unsigned long long total = atomicAdd(&g_mismatch_count, 0ULL);
                *out = (float)((double)total / (double)batch);
                g_mismatch_count = 0ULL;
                g_blocks_arrived = 0u;
            }
        }
    }
}

extern "C" void kernel_launch(void* const* d_in, const int* in_sizes, int n_in,
                              void* d_out, int out_size) {
    const float4* preds = (const float4*)d_in[0];   // [B, 8] f32
    const int* targets = (const int*)d_in[1];       // [B] int32
    int batch = in_sizes[0] / 8;
    float* out = (float*)d_out;

    const int threads = 256;
    // Persistent single wave: 148 SMs x 4 blocks/SM resident.
    int blocks = 148 * 4;
    path_loss_fused_kernel<<<blocks, threads>>>(preds, targets, out, batch);
}